// round 8
// baseline (speedup 1.0000x reference)
#include <cuda_runtime.h>
#include <cuda_bf16.h>

// Problem constants
#define BB   64      // batch (inputs)
#define MM   256     // modes
#define KK   4096    // spatial (64*64)

#define KC      128  // K per CTA chunk
#define KSPLIT  32   // KK / KC
#define MT      64   // modes per CTA (2 per lane)
#define MTILES  4    // MM / MT
#define F4R     32   // float4 / ulonglong2 units per row (KC/4)
#define NTHR    256
#define NCTA    (MTILES * KSPLIT)   // 128 <= 148 SMs: all co-resident
#define EPS_C   0.0009f

// Deterministic partial buffers (no cudaMalloc allowed)
__device__ __align__(16) float g_dot[KSPLIT * BB * MM];   // [s][b][m]  2 MB
__device__ __align__(16) float g_fss[KSPLIT * BB];        // [s][b]
__device__ __align__(16) float g_mss[KSPLIT * MM];        // [s][m]
__device__ unsigned int g_cnt;    // arrival counter (reset by last CTA)
__device__ unsigned int g_go;     // release flag     (reset after tail)
__device__ unsigned int g_done;   // tail-done counter

__device__ __forceinline__ unsigned long long fma2(unsigned long long a,
                                                   unsigned long long b,
                                                   unsigned long long c) {
    unsigned long long d;
    asm("fma.rn.f32x2 %0, %1, %2, %3;" : "=l"(d) : "l"(a), "l"(b), "l"(c));
    return d;
}

__device__ __forceinline__ float2 ull2f2(unsigned long long u) {
    float2 f;
    f.x = __uint_as_float((unsigned int)u);
    f.y = __uint_as_float((unsigned int)(u >> 32));
    return f;
}

// Fused: GEMM partials + last-64-to-arrive finalize (one CTA per b).
__global__ __launch_bounds__(NTHR)
void fused_kernel(const float* __restrict__ inp,
                  const float* __restrict__ mds,
                  float* __restrict__ out) {
    __shared__ float As[BB * KC];    // 32 KB, k-major, unswizzled
    __shared__ float Bs[MT * KC];    // 32 KB, k-major, kq ^ (m&7) swizzle
    __shared__ unsigned int s_rank;
    __shared__ float red[8];

    const int mt = blockIdx.x;
    const int ks = blockIdx.y;
    const int kbase = ks * KC;
    const int mbase = mt * MT;
    const int tid  = threadIdx.x;
    const int lane = tid & 31;
    const int w    = tid >> 5;       // 0..7

    float4* As4 = reinterpret_cast<float4*>(As);
    float4* Bs4 = reinterpret_cast<float4*>(Bs);

    // ---- stage A: 64 rows x 32 float4, coalesced ----
#pragma unroll
    for (int i = 0; i < 8; ++i) {
        int j  = i * NTHR + tid;
        int b  = j >> 5;
        int kq = j & 31;
        As4[b * F4R + kq] =
            *(reinterpret_cast<const float4*>(inp + (size_t)b * KK + kbase) + kq);
    }
    // ---- stage B: 64 rows x 32 float4, swizzled ----
#pragma unroll
    for (int i = 0; i < 8; ++i) {
        int j  = i * NTHR + tid;
        int m  = j >> 5;
        int kq = j & 31;
        Bs4[m * F4R + (kq ^ (m & 7))] =
            *(reinterpret_cast<const float4*>(mds + (size_t)(mbase + m) * KK + kbase) + kq);
    }
    __syncthreads();

    // ---- main loop: lane owns m = lane and lane+32; warp owns 8 b-rows ----
    const int c = lane & 7;
    const ulonglong2* As2 = reinterpret_cast<const ulonglong2*>(As);
    const ulonglong2* Bs2 = reinterpret_cast<const ulonglong2*>(Bs);

    unsigned long long acc[8][2];
#pragma unroll
    for (int r = 0; r < 8; ++r) { acc[r][0] = 0ull; acc[r][1] = 0ull; }

#pragma unroll 4
    for (int kq = 0; kq < F4R; ++kq) {
        ulonglong2 bv0 = Bs2[lane * F4R + (kq ^ c)];          // 4 phases
        ulonglong2 bv1 = Bs2[(lane + 32) * F4R + (kq ^ c)];   // 4 phases
#pragma unroll
        for (int r = 0; r < 8; ++r) {
            ulonglong2 av = As2[(8 * w + r) * F4R + kq];      // broadcast, 1 phase
            acc[r][0] = fma2(av.x, bv0.x, acc[r][0]);
            acc[r][0] = fma2(av.y, bv0.y, acc[r][0]);
            acc[r][1] = fma2(av.x, bv1.x, acc[r][1]);
            acc[r][1] = fma2(av.y, bv1.y, acc[r][1]);
        }
    }

    // ---- epilogue: reduce k-parity, coalesced partial-dot stores ----
#pragma unroll
    for (int r = 0; r < 8; ++r) {
        int b = 8 * w + r;
        float2 e0 = ull2f2(acc[r][0]);
        float2 e1 = ull2f2(acc[r][1]);
        g_dot[((size_t)ks * BB + b) * MM + mbase + lane]      = e0.x + e0.y;
        g_dot[((size_t)ks * BB + b) * MM + mbase + 32 + lane] = e1.x + e1.y;
    }

    // ---- partial squared norms (one warp per 32-float4 row) ----
#pragma unroll
    for (int r = 0; r < 8; ++r) {
        int m = 8 * w + r;
        float4 v = Bs4[m * F4R + (lane ^ (m & 7))];
        float s = v.x * v.x + v.y * v.y + v.z * v.z + v.w * v.w;
#pragma unroll
        for (int o = 16; o > 0; o >>= 1) s += __shfl_xor_sync(0xffffffffu, s, o);
        if (lane == 0) g_mss[ks * MM + mbase + m] = s;
    }
    if (mt == 0) {
#pragma unroll
        for (int r = 0; r < 8; ++r) {
            int b = 8 * w + r;
            float4 v = As4[b * F4R + lane];
            float s = v.x * v.x + v.y * v.y + v.z * v.z + v.w * v.w;
#pragma unroll
            for (int o = 16; o > 0; o >>= 1) s += __shfl_xor_sync(0xffffffffu, s, o);
            if (lane == 0) g_fss[ks * BB + b] = s;
        }
    }

    // ---- arrival: last 64 CTAs become finalizers (one b each) ----
    __syncthreads();
    if (tid == 0) {
        __threadfence();                                   // publish partials
        s_rank = atomicAdd(&g_cnt, 1u);                    // arrival rank
    }
    __syncthreads();
    const unsigned int rank = s_rank;

    if (rank < NCTA - BB) return;                          // early CTAs exit

    if (tid == 0) {
        if (rank == NCTA - 1) {                            // true last arriver
            g_cnt = 0;                                     // reset for next replay
            __threadfence();
            atomicExch(&g_go, 1u);                         // release
        } else {                                           // spin (acquire)
            unsigned int v;
            do {
                asm volatile("ld.acquire.gpu.u32 %0, [%1];"
                             : "=r"(v) : "l"(&g_go));
            } while (v == 0u);
        }
    }
    __syncthreads();

    // ---- finalize b = rank - (NCTA - BB); thread = mode m ----
    const int b = (int)rank - (NCTA - BB);
    const int m = tid;

    float dot = 0.f, mss = 0.f;
#pragma unroll 8
    for (int s = 0; s < KSPLIT; ++s) {
        dot += g_dot[((size_t)s * BB + b) * MM + m];       // coalesced across m
        mss += g_mss[s * MM + m];
    }
    float fss = 0.f;
#pragma unroll 8
    for (int s = 0; s < KSPLIT; ++s)
        fss += g_fss[s * BB + b];                          // uniform -> broadcast

    float fn = sqrtf(fss);
    float mn = sqrtf(mss);
    float cc = dot / (fn * mn);
    float dn = sqrtf(fmaxf(2.f - 2.f * cc, 0.f));
    float lum = (2.f * fn * mn + EPS_C) / (fss + mss + EPS_C);
    float metric = (1.f - (2.f - dn) * 0.5f * sqrtf(lum)) * 2.f;

#pragma unroll
    for (int o = 16; o > 0; o >>= 1)
        metric = fminf(metric, __shfl_xor_sync(0xffffffffu, metric, o));
    if ((tid & 31) == 0) red[tid >> 5] = metric;
    __syncthreads();
    if (tid == 0) {
        float v = red[0];
#pragma unroll
        for (int i = 1; i < 8; ++i) v = fminf(v, red[i]);
        out[b] = v;

        // tail bookkeeping: last finished finalizer resets flags for next replay
        unsigned int d = atomicAdd(&g_done, 1u);
        if (d == BB - 1) {
            g_done = 0u;
            atomicExch(&g_go, 0u);
        }
    }
}

extern "C" void kernel_launch(void* const* d_in, const int* in_sizes, int n_in,
                              void* d_out, int out_size) {
    const float* inp = (const float*)d_in[0];
    const float* mds = (const float*)d_in[1];
    if (in_sizes[0] > in_sizes[1]) {   // identify by element count
        const float* t = inp; inp = mds; mds = t;
    }

    dim3 grid(MTILES, KSPLIT);         // 4 x 32 = 128 CTAs, all co-resident
    fused_kernel<<<grid, NTHR>>>(inp, mds, (float*)d_out);
}